// round 1
// baseline (speedup 1.0000x reference)
#include <cuda_runtime.h>
#include <math.h>

#define NN 250000
#define EE 250000
#define D  128
#define HID 256
#define BR 64      // rows per block
#define KC 32      // k-chunk
#define HP (HID + 4)

// ---- persistent device scratch (no allocation allowed) ----
__device__ float g_Sp[(long long)NN * D];   // scatter-sum for S_p
__device__ float g_Sc[(long long)NN * D];   // scatter-sum for S_c
__device__ float g_edge[2 * D];             // [0:128)=edge_in, [128:256)=edge_out
__device__ int   g_cnt[2 * NN];             // counts: [0:N)=self, [N:2N)=parent
__device__ float g_inv[2 * NN];             // 1/max(cnt,1)

// ---------------------------------------------------------------------------
// tiny kernel: edge_in = MLP_E(1), edge_out = MLP_E(0)
// ---------------------------------------------------------------------------
__global__ void edge_const_k(const float* __restrict__ Ew1, const float* __restrict__ Eb1,
                             const float* __restrict__ Ew2, const float* __restrict__ Eb2) {
    __shared__ float hin[HID], hout[HID];
    int t = threadIdx.x;
    if (t < HID) {
        hin[t]  = fmaxf(Ew1[t] + Eb1[t], 0.f);  // input scalar = 1, Ew1 is [1,256]
        hout[t] = fmaxf(Eb1[t], 0.f);           // input scalar = 0
    }
    __syncthreads();
    if (t < D) {
        float si = 0.f, so = 0.f;
        for (int j = 0; j < HID; j++) {
            float w = Ew2[j * D + t];
            si += hin[j] * w;
            so += hout[j] * w;
        }
        g_edge[t]     = fmaxf(si + Eb2[t], 0.f);  // edge_in
        g_edge[D + t] = fmaxf(so + Eb2[t], 0.f);  // edge_out
    }
}

__global__ void zero_cnt_k() {
    int i = blockIdx.x * blockDim.x + threadIdx.x;
    if (i < 2 * NN) g_cnt[i] = 0;
}

__global__ void count_k(const int* __restrict__ si, const int* __restrict__ pi) {
    int e = blockIdx.x * blockDim.x + threadIdx.x;
    if (e < EE) {
        atomicAdd(&g_cnt[si[e]], 1);
        atomicAdd(&g_cnt[NN + pi[e]], 1);
    }
}

__global__ void inv_k() {
    int i = blockIdx.x * blockDim.x + threadIdx.x;
    if (i < 2 * NN) g_inv[i] = 1.f / fmaxf((float)g_cnt[i], 1.f);
}

__global__ void zero_SpSc_k() {
    long long n = (long long)NN * D / 4;
    float4 z = make_float4(0.f, 0.f, 0.f, 0.f);
    for (long long i = (long long)blockIdx.x * blockDim.x + threadIdx.x; i < n;
         i += (long long)gridDim.x * blockDim.x) {
        ((float4*)g_Sp)[i] = z;
        ((float4*)g_Sc)[i] = z;
    }
}

// ---------------------------------------------------------------------------
// Fused 2-layer MLP: Y[rows,128] = relu(relu(X[rows,KIN]@W1 + b1)@W2 + b2)
// MODE 0: X = srcA rows (batch_token);      epilogue: dst = y
// MODE 1: X = [hid[idxA], hid[idxB], edge]; epilogue: atomicAdd scatter by sidx
// MODE 2: X = [hid, Sp*inv+rm*st, Sc*inv+lm*et]; epilogue: dst += y (in place)
// TGT selects S_p vs S_c target + edge const half for MODE 1.
// ---------------------------------------------------------------------------
template <int KIN, int MODE, int TGT>
__global__ __launch_bounds__(256, 1) void mlp_k(
    int rows,
    const float* __restrict__ W1, const float* __restrict__ B1,
    const float* __restrict__ W2, const float* __restrict__ B2,
    const float* __restrict__ srcA,
    const int* __restrict__ idxA, const int* __restrict__ idxB,
    const int* __restrict__ sidx,
    const float* __restrict__ rmask, const float* __restrict__ lmask,
    const float* __restrict__ stok,  const float* __restrict__ etok,
    float* __restrict__ dst)
{
    extern __shared__ float sm[];
    float* Xs = sm;                       // BR x (KC+1)
    float* Ws = Xs + BR * (KC + 1);       // KC x HID  (reused as KC x D in phase B)
    float* Hs = Ws + KC * HID;            // BR x HP

    const int tid = threadIdx.x;
    const int tr = tid >> 5;              // 0..7 : row group
    const int tc = tid & 31;              // 0..31: col group
    const int row0 = blockIdx.x * BR;

    float acc[8][8];
#pragma unroll
    for (int i = 0; i < 8; i++)
#pragma unroll
        for (int j = 0; j < 8; j++) acc[i][j] = 0.f;

    // ---------------- phase A: H = relu(X @ W1 + b1) ----------------
    for (int kc = 0; kc < KIN; kc += KC) {
        // cooperative load of X tile (with fused gather)
#pragma unroll
        for (int i = 0; i < 8; i++) {
            int e  = i * 256 + tid;
            int r  = e >> 5;
            int cc = e & 31;
            int gr = row0 + r;
            if (gr >= rows) gr = rows - 1;
            int col = kc + cc;
            float v;
            if (MODE == 0) {
                v = srcA[(long long)gr * D + col];
            } else if (MODE == 1) {
                int seg = col >> 7, c2 = col & 127;
                if (seg == 0)      v = srcA[(long long)idxA[gr] * D + c2];
                else if (seg == 1) v = srcA[(long long)idxB[gr] * D + c2];
                else               v = g_edge[(TGT == 0 ? D : 0) + c2];
            } else {
                int seg = col >> 7, c2 = col & 127;
                if (seg == 0)      v = srcA[(long long)gr * D + c2];
                else if (seg == 1) v = g_Sp[(long long)gr * D + c2] * g_inv[gr]      + rmask[gr] * stok[c2];
                else               v = g_Sc[(long long)gr * D + c2] * g_inv[NN + gr] + lmask[gr] * etok[c2];
            }
            Xs[r * (KC + 1) + cc] = v;
        }
        // W1 chunk [KC][HID]
#pragma unroll
        for (int i = 0; i < 32; i++) {
            int e = i * 256 + tid;
            int kr = e >> 8, c = e & 255;
            Ws[kr * HID + c] = W1[(long long)(kc + kr) * HID + c];
        }
        __syncthreads();
#pragma unroll
        for (int k = 0; k < KC; k++) {
            float xa[8];
#pragma unroll
            for (int i = 0; i < 8; i++) xa[i] = Xs[(tr * 8 + i) * (KC + 1) + k];
            float4 w0 = *(const float4*)&Ws[k * HID + tc * 8];
            float4 w1 = *(const float4*)&Ws[k * HID + tc * 8 + 4];
            float wb[8] = {w0.x, w0.y, w0.z, w0.w, w1.x, w1.y, w1.z, w1.w};
#pragma unroll
            for (int i = 0; i < 8; i++)
#pragma unroll
                for (int j = 0; j < 8; j++) acc[i][j] = fmaf(xa[i], wb[j], acc[i][j]);
        }
        __syncthreads();
    }
    {
        float bb[8];
#pragma unroll
        for (int j = 0; j < 8; j++) bb[j] = B1[tc * 8 + j];
#pragma unroll
        for (int i = 0; i < 8; i++)
#pragma unroll
            for (int j = 0; j < 8; j++)
                Hs[(tr * 8 + i) * HP + tc * 8 + j] = fmaxf(acc[i][j] + bb[j], 0.f);
    }
    __syncthreads();

    // ---------------- phase B: Y = relu(H @ W2 + b2) ----------------
    float acc2[8][4];
#pragma unroll
    for (int i = 0; i < 8; i++)
#pragma unroll
        for (int j = 0; j < 4; j++) acc2[i][j] = 0.f;

    for (int kc = 0; kc < HID; kc += KC) {
#pragma unroll
        for (int i = 0; i < 16; i++) {
            int e = i * 256 + tid;
            int kr = e >> 7, c = e & 127;
            Ws[kr * D + c] = W2[(long long)(kc + kr) * D + c];
        }
        __syncthreads();
#pragma unroll
        for (int k = 0; k < KC; k++) {
            float xa[8];
#pragma unroll
            for (int i = 0; i < 8; i++) xa[i] = Hs[(tr * 8 + i) * HP + kc + k];
            float4 wv = *(const float4*)&Ws[k * D + tc * 4];
            float wb[4] = {wv.x, wv.y, wv.z, wv.w};
#pragma unroll
            for (int i = 0; i < 8; i++)
#pragma unroll
                for (int j = 0; j < 4; j++) acc2[i][j] = fmaf(xa[i], wb[j], acc2[i][j]);
        }
        __syncthreads();
    }

    // ---------------- epilogue ----------------
    float b2v[4];
#pragma unroll
    for (int j = 0; j < 4; j++) b2v[j] = B2[tc * 4 + j];

#pragma unroll
    for (int i = 0; i < 8; i++) {
        int gr = row0 + tr * 8 + i;
        if (gr < rows) {
            if (MODE == 1) {
                int t = sidx[gr];
                float* base = (TGT == 0 ? g_Sp : g_Sc) + (long long)t * D + tc * 4;
#pragma unroll
                for (int j = 0; j < 4; j++)
                    atomicAdd(&base[j], fmaxf(acc2[i][j] + b2v[j], 0.f));
            } else if (MODE == 0) {
#pragma unroll
                for (int j = 0; j < 4; j++)
                    dst[(long long)gr * D + tc * 4 + j] = fmaxf(acc2[i][j] + b2v[j], 0.f);
            } else {
#pragma unroll
                for (int j = 0; j < 4; j++) {
                    long long o = (long long)gr * D + tc * 4 + j;
                    dst[o] = dst[o] + fmaxf(acc2[i][j] + b2v[j], 0.f);
                }
            }
        }
    }
}

// ---------------------------------------------------------------------------
extern "C" void kernel_launch(void* const* d_in, const int* in_sizes, int n_in,
                              void* d_out, int out_size) {
    const float* bt    = (const float*)d_in[0];
    const int*   si    = (const int*)  d_in[1];
    const int*   pi    = (const int*)  d_in[2];
    const float* rmask = (const float*)d_in[3];
    const float* lmask = (const float*)d_in[4];
    const float* stok  = (const float*)d_in[5];
    const float* etok  = (const float*)d_in[6];
    const float* Vw1 = (const float*)d_in[7],  *Vb1 = (const float*)d_in[8];
    const float* Vw2 = (const float*)d_in[9],  *Vb2 = (const float*)d_in[10];
    const float* Ew1 = (const float*)d_in[11], *Eb1 = (const float*)d_in[12];
    const float* Ew2 = (const float*)d_in[13], *Eb2 = (const float*)d_in[14];
    const float* Pw1 = (const float*)d_in[15], *Pb1 = (const float*)d_in[16];
    const float* Pw2 = (const float*)d_in[17], *Pb2 = (const float*)d_in[18];
    const float* Cw1 = (const float*)d_in[19], *Cb1 = (const float*)d_in[20];
    const float* Cw2 = (const float*)d_in[21], *Cb2 = (const float*)d_in[22];
    const float* Aw1 = (const float*)d_in[23], *Ab1 = (const float*)d_in[24];
    const float* Aw2 = (const float*)d_in[25], *Ab2 = (const float*)d_in[26];

    float* hid = (float*)d_out;   // hidden lives in d_out (N*D f32)

    const int smem = (BR * (KC + 1) + KC * HID + BR * HP) * (int)sizeof(float);
    cudaFuncSetAttribute(mlp_k<128, 0, 0>, cudaFuncAttributeMaxDynamicSharedMemorySize, smem);
    cudaFuncSetAttribute(mlp_k<384, 1, 0>, cudaFuncAttributeMaxDynamicSharedMemorySize, smem);
    cudaFuncSetAttribute(mlp_k<384, 1, 1>, cudaFuncAttributeMaxDynamicSharedMemorySize, smem);
    cudaFuncSetAttribute(mlp_k<384, 2, 0>, cudaFuncAttributeMaxDynamicSharedMemorySize, smem);

    edge_const_k<<<1, HID>>>(Ew1, Eb1, Ew2, Eb2);
    zero_cnt_k<<<(2 * NN + 255) / 256, 256>>>();
    count_k<<<(EE + 255) / 256, 256>>>(si, pi);
    inv_k<<<(2 * NN + 255) / 256, 256>>>();

    const int gbN = (NN + BR - 1) / BR;
    const int gbE = (EE + BR - 1) / BR;

    // hidden = MLP_V(batch_token)
    mlp_k<128, 0, 0><<<gbN, 256, smem>>>(NN, Vw1, Vb1, Vw2, Vb2, bt,
                                         nullptr, nullptr, nullptr,
                                         nullptr, nullptr, nullptr, nullptr, hid);

    for (int h = 0; h < 3; h++) {
        zero_SpSc_k<<<1024, 256>>>();
        // S_p += MLP_P([hid[parent], hid[self], edge_out]) scattered by self
        mlp_k<384, 1, 0><<<gbE, 256, smem>>>(EE, Pw1, Pb1, Pw2, Pb2, hid,
                                             pi, si, si,
                                             nullptr, nullptr, nullptr, nullptr, nullptr);
        // S_c += MLP_C([hid[self], hid[parent], edge_in]) scattered by parent
        mlp_k<384, 1, 1><<<gbE, 256, smem>>>(EE, Cw1, Cb1, Cw2, Cb2, hid,
                                             si, pi, pi,
                                             nullptr, nullptr, nullptr, nullptr, nullptr);
        // hidden += MLP_A([hid, Sp*inv + rm*st, Sc*inv + lm*et])
        mlp_k<384, 2, 0><<<gbN, 256, smem>>>(NN, Aw1, Ab1, Aw2, Ab2, hid,
                                             nullptr, nullptr, nullptr,
                                             rmask, lmask, stok, etok, hid);
    }
}

// round 2
// speedup vs baseline: 1.0091x; 1.0091x over previous
#include <cuda_runtime.h>
#include <math.h>

#define NN 250000
#define EE 250000
#define D  128
#define HID 256
#define BR 64      // rows per block
#define KC 32      // k-chunk
#define HP (HID + 4)

// ---- persistent device scratch (no allocation allowed) ----
__device__ float g_Sp[(long long)NN * D];   // scatter-sum for S_p
__device__ float g_Sc[(long long)NN * D];   // scatter-sum for S_c
__device__ float g_edge[2 * D];             // [0:128)=edge_in, [128:256)=edge_out
__device__ int   g_cnt[2 * NN];             // counts: [0:N)=self, [N:2N)=parent
__device__ float g_inv[2 * NN];             // 1/max(cnt,1)

// ---------------------------------------------------------------------------
// tiny kernel: edge_in = MLP_E(1), edge_out = MLP_E(0)
// ---------------------------------------------------------------------------
__global__ void edge_const_k(const float* __restrict__ Ew1, const float* __restrict__ Eb1,
                             const float* __restrict__ Ew2, const float* __restrict__ Eb2) {
    __shared__ float hin[HID], hout[HID];
    int t = threadIdx.x;
    if (t < HID) {
        hin[t]  = fmaxf(Ew1[t] + Eb1[t], 0.f);  // input scalar = 1, Ew1 is [1,256]
        hout[t] = fmaxf(Eb1[t], 0.f);           // input scalar = 0
    }
    __syncthreads();
    if (t < D) {
        float si = 0.f, so = 0.f;
        for (int j = 0; j < HID; j++) {
            float w = Ew2[j * D + t];
            si += hin[j] * w;
            so += hout[j] * w;
        }
        g_edge[t]     = fmaxf(si + Eb2[t], 0.f);  // edge_in
        g_edge[D + t] = fmaxf(so + Eb2[t], 0.f);  // edge_out
    }
}

__global__ void zero_cnt_k() {
    int i = blockIdx.x * blockDim.x + threadIdx.x;
    if (i < 2 * NN) g_cnt[i] = 0;
}

__global__ void count_k(const int* __restrict__ si, const int* __restrict__ pi) {
    int e = blockIdx.x * blockDim.x + threadIdx.x;
    if (e < EE) {
        atomicAdd(&g_cnt[si[e]], 1);
        atomicAdd(&g_cnt[NN + pi[e]], 1);
    }
}

__global__ void inv_k() {
    int i = blockIdx.x * blockDim.x + threadIdx.x;
    if (i < 2 * NN) g_inv[i] = 1.f / fmaxf((float)g_cnt[i], 1.f);
}

__global__ void zero_SpSc_k() {
    long long n = (long long)NN * D / 4;
    float4 z = make_float4(0.f, 0.f, 0.f, 0.f);
    for (long long i = (long long)blockIdx.x * blockDim.x + threadIdx.x; i < n;
         i += (long long)gridDim.x * blockDim.x) {
        ((float4*)g_Sp)[i] = z;
        ((float4*)g_Sc)[i] = z;
    }
}

// ---------------------------------------------------------------------------
// Fused 2-layer MLP: Y[rows,128] = relu(relu(X[rows,KIN]@W1 + b1)@W2 + b2)
// MODE 0: X = srcA rows (batch_token);      epilogue: dst = y
// MODE 1: X = [hid[idxA], hid[idxB], edge]; epilogue: atomicAdd scatter by sidx
// MODE 2: X = [hid, Sp*inv+rm*st, Sc*inv+lm*et]; epilogue: dst += y (in place)
// TGT selects S_p vs S_c target + edge const half for MODE 1.
// ---------------------------------------------------------------------------
template <int KIN, int MODE, int TGT>
__global__ __launch_bounds__(256, 1) void mlp_k(
    int rows,
    const float* __restrict__ W1, const float* __restrict__ B1,
    const float* __restrict__ W2, const float* __restrict__ B2,
    const float* __restrict__ srcA,
    const int* __restrict__ idxA, const int* __restrict__ idxB,
    const int* __restrict__ sidx,
    const float* __restrict__ rmask, const float* __restrict__ lmask,
    const float* __restrict__ stok,  const float* __restrict__ etok,
    float* __restrict__ dst)
{
    extern __shared__ float sm[];
    float* Xs = sm;                       // BR x (KC+1)
    float* Ws = Xs + BR * (KC + 1);       // KC x HID  (reused as KC x D in phase B)
    float* Hs = Ws + KC * HID;            // BR x HP

    const int tid = threadIdx.x;
    const int tr = tid >> 5;              // 0..7 : row group
    const int tc = tid & 31;              // 0..31: col group
    const int row0 = blockIdx.x * BR;

    float acc[8][8];
#pragma unroll
    for (int i = 0; i < 8; i++)
#pragma unroll
        for (int j = 0; j < 8; j++) acc[i][j] = 0.f;

    // ---------------- phase A: H = relu(X @ W1 + b1) ----------------
    for (int kc = 0; kc < KIN; kc += KC) {
        // cooperative load of X tile (with fused gather)
#pragma unroll
        for (int i = 0; i < 8; i++) {
            int e  = i * 256 + tid;
            int r  = e >> 5;
            int cc = e & 31;
            int gr = row0 + r;
            if (gr >= rows) gr = rows - 1;
            int col = kc + cc;
            float v;
            if (MODE == 0) {
                v = srcA[(long long)gr * D + col];
            } else if (MODE == 1) {
                int seg = col >> 7, c2 = col & 127;
                if (seg == 0)      v = srcA[(long long)idxA[gr] * D + c2];
                else if (seg == 1) v = srcA[(long long)idxB[gr] * D + c2];
                else               v = g_edge[(TGT == 0 ? D : 0) + c2];
            } else {
                int seg = col >> 7, c2 = col & 127;
                if (seg == 0)      v = srcA[(long long)gr * D + c2];
                else if (seg == 1) v = g_Sp[(long long)gr * D + c2] * g_inv[gr]      + rmask[gr] * stok[c2];
                else               v = g_Sc[(long long)gr * D + c2] * g_inv[NN + gr] + lmask[gr] * etok[c2];
            }
            Xs[r * (KC + 1) + cc] = v;
        }
        // W1 chunk [KC][HID]
#pragma unroll
        for (int i = 0; i < 32; i++) {
            int e = i * 256 + tid;
            int kr = e >> 8, c = e & 255;
            Ws[kr * HID + c] = W1[(long long)(kc + kr) * HID + c];
        }
        __syncthreads();
#pragma unroll
        for (int k = 0; k < KC; k++) {
            float xa[8];
#pragma unroll
            for (int i = 0; i < 8; i++) xa[i] = Xs[(tr * 8 + i) * (KC + 1) + k];
            float4 w0 = *(const float4*)&Ws[k * HID + tc * 8];
            float4 w1 = *(const float4*)&Ws[k * HID + tc * 8 + 4];
            float wb[8] = {w0.x, w0.y, w0.z, w0.w, w1.x, w1.y, w1.z, w1.w};
#pragma unroll
            for (int i = 0; i < 8; i++)
#pragma unroll
                for (int j = 0; j < 8; j++) acc[i][j] = fmaf(xa[i], wb[j], acc[i][j]);
        }
        __syncthreads();
    }
    {
        float bb[8];
#pragma unroll
        for (int j = 0; j < 8; j++) bb[j] = B1[tc * 8 + j];
#pragma unroll
        for (int i = 0; i < 8; i++)
#pragma unroll
            for (int j = 0; j < 8; j++)
                Hs[(tr * 8 + i) * HP + tc * 8 + j] = fmaxf(acc[i][j] + bb[j], 0.f);
    }
    __syncthreads();

    // ---------------- phase B: Y = relu(H @ W2 + b2) ----------------
    float acc2[8][4];
#pragma unroll
    for (int i = 0; i < 8; i++)
#pragma unroll
        for (int j = 0; j < 4; j++) acc2[i][j] = 0.f;

    for (int kc = 0; kc < HID; kc += KC) {
#pragma unroll
        for (int i = 0; i < 16; i++) {
            int e = i * 256 + tid;
            int kr = e >> 7, c = e & 127;
            Ws[kr * D + c] = W2[(long long)(kc + kr) * D + c];
        }
        __syncthreads();
#pragma unroll
        for (int k = 0; k < KC; k++) {
            float xa[8];
#pragma unroll
            for (int i = 0; i < 8; i++) xa[i] = Hs[(tr * 8 + i) * HP + kc + k];
            float4 wv = *(const float4*)&Ws[k * D + tc * 4];
            float wb[4] = {wv.x, wv.y, wv.z, wv.w};
#pragma unroll
            for (int i = 0; i < 8; i++)
#pragma unroll
                for (int j = 0; j < 4; j++) acc2[i][j] = fmaf(xa[i], wb[j], acc2[i][j]);
        }
        __syncthreads();
    }

    // ---------------- epilogue ----------------
    float b2v[4];
#pragma unroll
    for (int j = 0; j < 4; j++) b2v[j] = B2[tc * 4 + j];

#pragma unroll
    for (int i = 0; i < 8; i++) {
        int gr = row0 + tr * 8 + i;
        if (gr < rows) {
            if (MODE == 1) {
                int t = sidx[gr];
                float* base = (TGT == 0 ? g_Sp : g_Sc) + (long long)t * D + tc * 4;
#pragma unroll
                for (int j = 0; j < 4; j++)
                    atomicAdd(&base[j], fmaxf(acc2[i][j] + b2v[j], 0.f));
            } else if (MODE == 0) {
#pragma unroll
                for (int j = 0; j < 4; j++)
                    dst[(long long)gr * D + tc * 4 + j] = fmaxf(acc2[i][j] + b2v[j], 0.f);
            } else {
#pragma unroll
                for (int j = 0; j < 4; j++) {
                    long long o = (long long)gr * D + tc * 4 + j;
                    dst[o] = dst[o] + fmaxf(acc2[i][j] + b2v[j], 0.f);
                }
            }
        }
    }
}

// ---------------------------------------------------------------------------
extern "C" void kernel_launch(void* const* d_in, const int* in_sizes, int n_in,
                              void* d_out, int out_size) {
    const float* bt    = (const float*)d_in[0];
    const int*   si    = (const int*)  d_in[1];
    const int*   pi    = (const int*)  d_in[2];
    const float* rmask = (const float*)d_in[3];
    const float* lmask = (const float*)d_in[4];
    const float* stok  = (const float*)d_in[5];
    const float* etok  = (const float*)d_in[6];
    const float* Vw1 = (const float*)d_in[7],  *Vb1 = (const float*)d_in[8];
    const float* Vw2 = (const float*)d_in[9],  *Vb2 = (const float*)d_in[10];
    const float* Ew1 = (const float*)d_in[11], *Eb1 = (const float*)d_in[12];
    const float* Ew2 = (const float*)d_in[13], *Eb2 = (const float*)d_in[14];
    const float* Pw1 = (const float*)d_in[15], *Pb1 = (const float*)d_in[16];
    const float* Pw2 = (const float*)d_in[17], *Pb2 = (const float*)d_in[18];
    const float* Cw1 = (const float*)d_in[19], *Cb1 = (const float*)d_in[20];
    const float* Cw2 = (const float*)d_in[21], *Cb2 = (const float*)d_in[22];
    const float* Aw1 = (const float*)d_in[23], *Ab1 = (const float*)d_in[24];
    const float* Aw2 = (const float*)d_in[25], *Ab2 = (const float*)d_in[26];

    float* hid = (float*)d_out;   // hidden lives in d_out (N*D f32)

    const int smem = (BR * (KC + 1) + KC * HID + BR * HP) * (int)sizeof(float);
    cudaFuncSetAttribute(mlp_k<128, 0, 0>, cudaFuncAttributeMaxDynamicSharedMemorySize, smem);
    cudaFuncSetAttribute(mlp_k<384, 1, 0>, cudaFuncAttributeMaxDynamicSharedMemorySize, smem);
    cudaFuncSetAttribute(mlp_k<384, 1, 1>, cudaFuncAttributeMaxDynamicSharedMemorySize, smem);
    cudaFuncSetAttribute(mlp_k<384, 2, 0>, cudaFuncAttributeMaxDynamicSharedMemorySize, smem);

    edge_const_k<<<1, HID>>>(Ew1, Eb1, Ew2, Eb2);
    zero_cnt_k<<<(2 * NN + 255) / 256, 256>>>();
    count_k<<<(EE + 255) / 256, 256>>>(si, pi);
    inv_k<<<(2 * NN + 255) / 256, 256>>>();

    const int gbN = (NN + BR - 1) / BR;
    const int gbE = (EE + BR - 1) / BR;

    // hidden = MLP_V(batch_token)
    mlp_k<128, 0, 0><<<gbN, 256, smem>>>(NN, Vw1, Vb1, Vw2, Vb2, bt,
                                         nullptr, nullptr, nullptr,
                                         nullptr, nullptr, nullptr, nullptr, hid);

    for (int h = 0; h < 3; h++) {
        zero_SpSc_k<<<1024, 256>>>();
        // S_p += MLP_P([hid[parent], hid[self], edge_out]) scattered by self
        mlp_k<384, 1, 0><<<gbE, 256, smem>>>(EE, Pw1, Pb1, Pw2, Pb2, hid,
                                             pi, si, si,
                                             nullptr, nullptr, nullptr, nullptr, nullptr);
        // S_c += MLP_C([hid[self], hid[parent], edge_in]) scattered by parent
        mlp_k<384, 1, 1><<<gbE, 256, smem>>>(EE, Cw1, Cb1, Cw2, Cb2, hid,
                                             si, pi, pi,
                                             nullptr, nullptr, nullptr, nullptr, nullptr);
        // hidden += MLP_A([hid, Sp*inv + rm*st, Sc*inv + lm*et])
        mlp_k<384, 2, 0><<<gbN, 256, smem>>>(NN, Aw1, Ab1, Aw2, Ab2, hid,
                                             nullptr, nullptr, nullptr,
                                             rmask, lmask, stok, etok, hid);
    }
}

// round 4
// speedup vs baseline: 1.3630x; 1.3507x over previous
#include <cuda_runtime.h>
#include <cstdint>
#include <math.h>

#define NN 250000
#define EE 250000
#define D   128
#define HID 256
#define BR  64
#define KC  32
#define XS  34            // Xs/Wst row stride (floats): even, ≡2 mod 4 → conflict-free LDS.64
#define HS  258           // Hs row stride

// ---- persistent device scratch ----
__device__ float g_Sp[(size_t)NN * D];   // zero-init; kept zeroed by aggr kernel
__device__ float g_Sc[(size_t)NN * D];
__device__ int   g_cnt[2 * NN];
__device__ float g_inv[2 * NN];
__device__ float g_edge[2 * D];          // [0:128)=edge_in, [128:256)=edge_out
__device__ float g_b1P[HID];
__device__ float g_b1C[HID];

__device__ __forceinline__ void ffma2(uint64_t& acc, uint64_t x, uint64_t w) {
    asm("fma.rn.f32x2 %0, %1, %2, %0;" : "+l"(acc) : "l"(x), "l"(w));
}
__device__ __forceinline__ float sum2(uint64_t v) {
    uint32_t lo, hi;
    asm("mov.b64 {%0,%1}, %2;" : "=r"(lo), "=r"(hi) : "l"(v));
    return __uint_as_float(lo) + __uint_as_float(hi);
}
__device__ __forceinline__ void redadd(float* p, float v) {
    asm volatile("red.global.add.f32 [%0], %1;" :: "l"(p), "f"(v) : "memory");
}

// ---------------- setup kernels ----------------
__global__ void edge_const_k(const float* __restrict__ Ew1, const float* __restrict__ Eb1,
                             const float* __restrict__ Ew2, const float* __restrict__ Eb2) {
    __shared__ float hin[HID], hout[HID];
    int t = threadIdx.x;
    hin[t]  = fmaxf(Ew1[t] + Eb1[t], 0.f);
    hout[t] = fmaxf(Eb1[t], 0.f);
    __syncthreads();
    if (t < D) {
        float si = 0.f, so = 0.f;
        for (int j = 0; j < HID; j++) { float w = Ew2[j * D + t]; si += hin[j] * w; so += hout[j] * w; }
        g_edge[t]     = fmaxf(si + Eb2[t], 0.f);   // edge_in
        g_edge[D + t] = fmaxf(so + Eb2[t], 0.f);   // edge_out
    }
}
// fold edge-constant input columns into layer-1 biases of P and C
__global__ void fold_bias_k(const float* __restrict__ Pw1, const float* __restrict__ Pb1,
                            const float* __restrict__ Cw1, const float* __restrict__ Cb1) {
    int j = threadIdx.x;  // 256
    float sp = Pb1[j], sc = Cb1[j];
    for (int c = 0; c < D; c++) {
        sp += g_edge[D + c] * Pw1[(size_t)(2 * D + c) * HID + j];  // edge_out -> P
        sc += g_edge[c]     * Cw1[(size_t)(2 * D + c) * HID + j];  // edge_in  -> C
    }
    g_b1P[j] = sp; g_b1C[j] = sc;
}
__global__ void zero_cnt_k() {
    int i = blockIdx.x * blockDim.x + threadIdx.x;
    if (i < 2 * NN) g_cnt[i] = 0;
}
__global__ void count_k(const int* __restrict__ si, const int* __restrict__ pi) {
    int e = blockIdx.x * blockDim.x + threadIdx.x;
    if (e < EE) { atomicAdd(&g_cnt[si[e]], 1); atomicAdd(&g_cnt[NN + pi[e]], 1); }
}
__global__ void inv_k() {
    int i = blockIdx.x * blockDim.x + threadIdx.x;
    if (i < 2 * NN) g_inv[i] = 1.f / fmaxf((float)g_cnt[i], 1.f);
}

// ---------------------------------------------------------------------------
// Fused 2-layer MLP, packed-f32x2 micro-kernel.
// Lanes of each f32x2 accumulator hold k-even/k-odd partial sums.
// MODE 0: X = srcA rows [N,128];                 out: dst = y
// MODE 1: X = [hid[idxA], hid[idxB]] (K=256);    out: red-scatter by sidx (bias folded)
// MODE 2: X = [hid, Sp*inv+rm*st, Sc*inv+lm*et]; out: dst += y; re-zero Sp/Sc rows
// ---------------------------------------------------------------------------
template <int KIN, int MODE, int TGT>
__global__ __launch_bounds__(256, 1) void mlp2_k(
    int rows,
    const float* __restrict__ W1, const float* __restrict__ B1a,
    const float* __restrict__ W2, const float* __restrict__ B2,
    const float* __restrict__ srcA,
    const int* __restrict__ idxA, const int* __restrict__ idxB, const int* __restrict__ sidx,
    const float* __restrict__ rmask, const float* __restrict__ lmask,
    const float* __restrict__ stok,  const float* __restrict__ etok,
    float* __restrict__ dst)
{
    extern __shared__ float sm[];
    float* Xs  = sm;                     // BR x XS
    float* Wst = Xs + BR * XS;           // 256 x XS (transposed weight chunk)
    float* Hs  = Wst + HID * XS;         // BR x HS

    const float* B1 = (MODE == 1) ? (TGT == 0 ? (const float*)g_b1P : (const float*)g_b1C) : B1a;
    const int tid  = threadIdx.x;
    const int wid  = tid >> 5, lane = tid & 31;
    const int row0 = blockIdx.x * BR;

    // ---------------- phase A: H = relu(X @ W1 + b1), N=256 ----------------
    uint64_t acc[8][8];
#pragma unroll
    for (int i = 0; i < 8; i++)
#pragma unroll
        for (int m = 0; m < 8; m++) acc[i][m] = 0ull;

    for (int kc = 0; kc < KIN; kc += KC) {
        // stage X tile [64][32] (k contiguous)
#pragma unroll
        for (int i = 0; i < 8; i++) {
            int e = i * 256 + tid;
            int r = e >> 5, cc = e & 31;
            int gr = row0 + r; if (gr >= rows) gr = rows - 1;
            int col = kc + cc;
            float v;
            if (MODE == 0) {
                v = srcA[(size_t)gr * D + col];
            } else if (MODE == 1) {
                int c2 = col & 127;
                int idx = (col < 128 ? idxA : idxB)[gr];
                v = srcA[(size_t)idx * D + c2];
            } else {
                int c2 = col & 127;
                if (col < 128)      v = srcA[(size_t)gr * D + c2];
                else if (col < 256) v = g_Sp[(size_t)gr * D + c2] * g_inv[gr]      + rmask[gr] * stok[c2];
                else                v = g_Sc[(size_t)gr * D + c2] * g_inv[NN + gr] + lmask[gr] * etok[c2];
            }
            Xs[r * XS + cc] = v;
        }
        // stage W1 chunk transposed: Wst[n][kk] = W1[kc+kk][n]
#pragma unroll
        for (int i = 0; i < 32; i++) {
            int e = i * 256 + tid;
            int kk = e >> 8, n = e & 255;
            Wst[n * XS + kk] = W1[(size_t)(kc + kk) * HID + n];
        }
        __syncthreads();
#pragma unroll
        for (int kp = 0; kp < 16; kp++) {
            uint64_t xp[8];
#pragma unroll
            for (int i = 0; i < 8; i++)
                xp[i] = *(const uint64_t*)&Xs[(wid * 8 + i) * XS + kp * 2];
#pragma unroll
            for (int m = 0; m < 8; m++) {
                uint64_t wv = *(const uint64_t*)&Wst[(m * 32 + lane) * XS + kp * 2];
#pragma unroll
                for (int i = 0; i < 8; i++) ffma2(acc[i][m], xp[i], wv);
            }
        }
        __syncthreads();
    }

    if (MODE == 2) {   // re-zero consumed Sp/Sc rows (block-exclusive, replay-invariant)
        float4 z = make_float4(0.f, 0.f, 0.f, 0.f);
        for (int i = tid; i < BR * 32; i += 256) {
            int gr = row0 + (i >> 5);
            if (gr < rows) {
                ((float4*)g_Sp)[(size_t)gr * 32 + (i & 31)] = z;
                ((float4*)g_Sc)[(size_t)gr * 32 + (i & 31)] = z;
            }
        }
    }

    // epilogue A -> Hs
#pragma unroll
    for (int m = 0; m < 8; m++) {
        int col = m * 32 + lane;
        float b = B1[col];
#pragma unroll
        for (int i = 0; i < 8; i++)
            Hs[(wid * 8 + i) * HS + col] = fmaxf(sum2(acc[i][m]) + b, 0.f);
    }
    __syncthreads();

    // ---------------- phase B: Y = relu(H @ W2 + b2), N=128 ----------------
    uint64_t acc2[8][4];
#pragma unroll
    for (int i = 0; i < 8; i++)
#pragma unroll
        for (int m = 0; m < 4; m++) acc2[i][m] = 0ull;

    for (int kc = 0; kc < HID; kc += KC) {
#pragma unroll
        for (int i = 0; i < 16; i++) {
            int e = i * 256 + tid;
            int kk = e >> 7, n = e & 127;
            Wst[n * XS + kk] = W2[(size_t)(kc + kk) * D + n];
        }
        __syncthreads();
#pragma unroll
        for (int kp = 0; kp < 16; kp++) {
            uint64_t xp[8];
#pragma unroll
            for (int i = 0; i < 8; i++)
                xp[i] = *(const uint64_t*)&Hs[(wid * 8 + i) * HS + kc + kp * 2];
#pragma unroll
            for (int m = 0; m < 4; m++) {
                uint64_t wv = *(const uint64_t*)&Wst[(m * 32 + lane) * XS + kp * 2];
#pragma unroll
                for (int i = 0; i < 8; i++) ffma2(acc2[i][m], xp[i], wv);
            }
        }
        __syncthreads();
    }

    // ---------------- epilogue B ----------------
#pragma unroll
    for (int i = 0; i < 8; i++) {
        int gr = row0 + wid * 8 + i;
        if (gr >= rows) continue;
        int t = 0;
        if (MODE == 1) t = sidx[gr];
#pragma unroll
        for (int m = 0; m < 4; m++) {
            int col = m * 32 + lane;
            float y = fmaxf(sum2(acc2[i][m]) + B2[col], 0.f);
            if (MODE == 1) {
                redadd((TGT == 0 ? g_Sp : g_Sc) + (size_t)t * D + col, y);
            } else if (MODE == 0) {
                dst[(size_t)gr * D + col] = y;
            } else {
                size_t o = (size_t)gr * D + col;
                dst[o] = dst[o] + y;
            }
        }
    }
}

// ---------------------------------------------------------------------------
extern "C" void kernel_launch(void* const* d_in, const int* in_sizes, int n_in,
                              void* d_out, int out_size) {
    const float* bt    = (const float*)d_in[0];
    const int*   si    = (const int*)  d_in[1];
    const int*   pi    = (const int*)  d_in[2];
    const float* rmask = (const float*)d_in[3];
    const float* lmask = (const float*)d_in[4];
    const float* stok  = (const float*)d_in[5];
    const float* etok  = (const float*)d_in[6];
    const float* Vw1 = (const float*)d_in[7],  *Vb1 = (const float*)d_in[8];
    const float* Vw2 = (const float*)d_in[9],  *Vb2 = (const float*)d_in[10];
    const float* Ew1 = (const float*)d_in[11], *Eb1 = (const float*)d_in[12];
    const float* Ew2 = (const float*)d_in[13], *Eb2 = (const float*)d_in[14];
    const float* Pw1 = (const float*)d_in[15], *Pb1 = (const float*)d_in[16];
    const float* Pw2 = (const float*)d_in[17], *Pb2 = (const float*)d_in[18];
    const float* Cw1 = (const float*)d_in[19], *Cb1 = (const float*)d_in[20];
    const float* Cw2 = (const float*)d_in[21], *Cb2 = (const float*)d_in[22];
    const float* Aw1 = (const float*)d_in[23], *Ab1 = (const float*)d_in[24];
    const float* Aw2 = (const float*)d_in[25], *Ab2 = (const float*)d_in[26];
    float* hid = (float*)d_out;

    const int smem = (BR * XS + HID * XS + BR * HS) * (int)sizeof(float);
    cudaFuncSetAttribute(mlp2_k<128, 0, 0>, cudaFuncAttributeMaxDynamicSharedMemorySize, smem);
    cudaFuncSetAttribute(mlp2_k<256, 1, 0>, cudaFuncAttributeMaxDynamicSharedMemorySize, smem);
    cudaFuncSetAttribute(mlp2_k<256, 1, 1>, cudaFuncAttributeMaxDynamicSharedMemorySize, smem);
    cudaFuncSetAttribute(mlp2_k<384, 2, 0>, cudaFuncAttributeMaxDynamicSharedMemorySize, smem);

    edge_const_k<<<1, 256>>>(Ew1, Eb1, Ew2, Eb2);
    fold_bias_k<<<1, 256>>>(Pw1, Pb1, Cw1, Cb1);
    zero_cnt_k<<<(2 * NN + 255) / 256, 256>>>();
    count_k<<<(EE + 255) / 256, 256>>>(si, pi);
    inv_k<<<(2 * NN + 255) / 256, 256>>>();

    const int gb = (NN + BR - 1) / BR;   // == for EE too

    // hidden = MLP_V(batch_token)
    mlp2_k<128, 0, 0><<<gb, 256, smem>>>(NN, Vw1, Vb1, Vw2, Vb2, bt,
                                         nullptr, nullptr, nullptr,
                                         nullptr, nullptr, nullptr, nullptr, hid);
    for (int h = 0; h < 3; h++) {
        // S_p += MLP_P([hid[parent], hid[self]]) scattered by self (edge folded into bias)
        mlp2_k<256, 1, 0><<<gb, 256, smem>>>(EE, Pw1, nullptr, Pw2, Pb2, hid,
                                             pi, si, si,
                                             nullptr, nullptr, nullptr, nullptr, nullptr);
        // S_c += MLP_C([hid[self], hid[parent]]) scattered by parent
        mlp2_k<256, 1, 1><<<gb, 256, smem>>>(EE, Cw1, nullptr, Cw2, Cb2, hid,
                                             si, pi, pi,
                                             nullptr, nullptr, nullptr, nullptr, nullptr);
        // hidden += MLP_A([hid, Sp*inv + rm*st, Sc*inv + lm*et]); re-zeros Sp/Sc
        mlp2_k<384, 2, 0><<<gb, 256, smem>>>(NN, Aw1, Ab1, Aw2, Ab2, hid,
                                             nullptr, nullptr, nullptr,
                                             rmask, lmask, stok, etok, hid);
    }
}